// round 5
// baseline (speedup 1.0000x reference)
#include <cuda_runtime.h>
#include <cstdint>

// Column-major fused DCN CrossLayer, software-pipelined.
// Thread t owns float4 column t; weights in registers.
// Per 4-row iteration: dots -> PREFETCH next 4 rows -> warp reduce ->
// ONE syncthreads -> all-warp redundant combine -> store. red[] double-buffered.

#define F_DIM 1024
#define NVEC  256
#define THREADS 256
#define NWARPS 8
#define R 4
#define CHUNK 32
#define ITERS (CHUNK / R)

__device__ __forceinline__ float dot4(float4 a, float4 b, float acc) {
    return fmaf(a.x, b.x, fmaf(a.y, b.y, fmaf(a.z, b.z, fmaf(a.w, b.w, acc))));
}

__global__ __launch_bounds__(THREADS)
void cross_pipe_kernel(const float* __restrict__ x,
                       const float* __restrict__ kernels,
                       const float* __restrict__ bias,
                       float* __restrict__ out,
                       int B)
{
    __shared__ float red[2][12][NWARPS];
    __shared__ float sc01, sc012;

    const int t   = threadIdx.x;        // float4 column 0..255
    const int wid = t >> 5;
    const int lid = t & 31;

    // ---- One-time: per-column weights into registers ----
    const float4* __restrict__ k4 = reinterpret_cast<const float4*>(kernels);
    const float4* __restrict__ b4 = reinterpret_cast<const float4*>(bias);
    const float4 w0 = __ldg(&k4[t]);
    const float4 w1 = __ldg(&k4[NVEC + t]);
    const float4 w2 = __ldg(&k4[2 * NVEC + t]);
    float4 b0 = __ldg(&b4[t]);
    float4 b1 = __ldg(&b4[NVEC + t]);
    float4 b2 = __ldg(&b4[2 * NVEC + t]);
    float4 bs;
    bs.x = b0.x + b1.x + b2.x;
    bs.y = b0.y + b1.y + b2.y;
    bs.z = b0.z + b1.z + b2.z;
    bs.w = b0.w + b1.w + b2.w;

    // cross constants: c01 = b0.w1, c012 = (b0+b1).w2
    {
        float pc01  = dot4(b0, w1, 0.f);
        float4 b01;
        b01.x = b0.x + b1.x; b01.y = b0.y + b1.y;
        b01.z = b0.z + b1.z; b01.w = b0.w + b1.w;
        float pc012 = dot4(b01, w2, 0.f);
        #pragma unroll
        for (int off = 16; off; off >>= 1) {
            pc01  += __shfl_xor_sync(0xFFFFFFFFu, pc01,  off);
            pc012 += __shfl_xor_sync(0xFFFFFFFFu, pc012, off);
        }
        if (lid == 0) { red[0][0][wid] = pc01; red[0][1][wid] = pc012; }
        __syncthreads();
        if (t == 0) {
            float a = 0.f, b = 0.f;
            #pragma unroll
            for (int i = 0; i < NWARPS; i++) { a += red[0][0][i]; b += red[0][1][i]; }
            sc01 = a; sc012 = b;
        }
        __syncthreads();
    }
    const float c01  = sc01;
    const float c012 = sc012;

    const float4* __restrict__ x4 = reinterpret_cast<const float4*>(x);
    float4* __restrict__ o4       = reinterpret_cast<float4*>(out);

    const int row0 = blockIdx.x * CHUNK;

    // ---- Prologue: load first tile ----
    float4 xc[R];
    #pragma unroll
    for (int r = 0; r < R; r++) {
        const int rr = (row0 + r < B) ? (row0 + r) : (B - 1);
        xc[r] = __ldcs(&x4[(size_t)rr * NVEC + t]);
    }

    #pragma unroll 1
    for (int it = 0; it < ITERS; ++it) {
        const int rbase = row0 + it * R;

        // ---- Dots from current tile ----
        float p[3 * R];
        #pragma unroll
        for (int r = 0; r < R; r++) {
            p[r]         = dot4(xc[r], w0, 0.f);
            p[R + r]     = dot4(xc[r], w1, 0.f);
            p[2 * R + r] = dot4(xc[r], w2, 0.f);
        }

        // ---- Prefetch next tile (in flight across reduce+barrier) ----
        float4 xn[R];
        if (it + 1 < ITERS) {
            const int nb = row0 + (it + 1) * R;
            #pragma unroll
            for (int r = 0; r < R; r++) {
                const int rr = (nb + r < B) ? (nb + r) : (B - 1);
                xn[r] = __ldcs(&x4[(size_t)rr * NVEC + t]);
            }
        }

        // ---- Warp reduce 12 partials ----
        #pragma unroll
        for (int off = 16; off; off >>= 1) {
            #pragma unroll
            for (int j = 0; j < 3 * R; j++)
                p[j] += __shfl_xor_sync(0xFFFFFFFFu, p[j], off);
        }
        const int buf = it & 1;
        if (lid == 0) {
            #pragma unroll
            for (int j = 0; j < 3 * R; j++) red[buf][j][wid] = p[j];
        }
        __syncthreads();

        // ---- All-warp redundant combine ----
        float val = 0.f;
        if (lid < 12) {
            #pragma unroll
            for (int w = 0; w < NWARPS; w++) val += red[buf][lid][w];
        }
        float alpha[R];
        #pragma unroll
        for (int r = 0; r < R; r++) {
            const float d0 = __shfl_sync(0xFFFFFFFFu, val, r);
            const float d1 = __shfl_sync(0xFFFFFFFFu, val, R + r);
            const float d2 = __shfl_sync(0xFFFFFFFFu, val, 2 * R + r);
            const float t1 = 1.f + d0;
            const float s1 = fmaf(t1, d1, c01);
            const float t2 = t1 + s1;
            const float s2 = fmaf(t2, d2, c012);
            alpha[r] = t2 + s2;
        }

        // ---- Store from current tile ----
        #pragma unroll
        for (int r = 0; r < R; r++) {
            const int rr = rbase + r;
            if (rr < B) {
                float4 o;
                o.x = fmaf(alpha[r], xc[r].x, bs.x);
                o.y = fmaf(alpha[r], xc[r].y, bs.y);
                o.z = fmaf(alpha[r], xc[r].z, bs.z);
                o.w = fmaf(alpha[r], xc[r].w, bs.w);
                __stcs(&o4[(size_t)rr * NVEC + t], o);
            }
        }

        // ---- Rotate ----
        #pragma unroll
        for (int r = 0; r < R; r++) xc[r] = xn[r];
    }
}

extern "C" void kernel_launch(void* const* d_in, const int* in_sizes, int n_in,
                              void* d_out, int out_size)
{
    const float* x       = (const float*)d_in[0];
    const float* kernels = (const float*)d_in[1];
    const float* bias    = (const float*)d_in[2];
    float* out           = (float*)d_out;

    const int B = in_sizes[0] / F_DIM;
    const int grid = (B + CHUNK - 1) / CHUNK;
    cross_pipe_kernel<<<grid, THREADS>>>(x, kernels, bias, out, B);
}